// round 3
// baseline (speedup 1.0000x reference)
#include <cuda_runtime.h>
#include <math.h>

#define BATCH 64
#define NN    256
#define MM    512
#define SIGMA 1e-6f
#define RHO   0.1f
#define ALPHA 1.6f
#define ITERS 200
#define TRI   32896   // 256*257/2

__device__ float g_M[BATCH * TRI];
__device__ float g_Linv[BATCH * TRI];
__device__ float g_Y[BATCH * NN * MM];
__device__ float g_g[BATCH * NN];
__device__ float g_S[BATCH * NN];

__device__ __forceinline__ int offr(int i) { return (i * (i + 1)) >> 1; }
__constant__ int c_ti[10] = {0,1,1,2,2,2,3,3,3,3};
__constant__ int c_tj[10] = {0,0,1,0,1,2,0,1,2,3};

// K1: M = diag(P)+sigma*I+rho*A^T A (packed lower). 64x64 tiles, 4x4 regs.
__global__ __launch_bounds__(256) void k1_buildM(const float* __restrict__ Pv,
                                                 const float* __restrict__ Av)
{
    int p = blockIdx.x, b = blockIdx.y;
    int i0 = c_ti[p] * 64, j0 = c_tj[p] * 64;
    __shared__ float As[16][64], Bs[16][64];
    const float* A = Av + (size_t)b * (MM * NN);
    float acc[4][4];
#pragma unroll
    for (int a = 0; a < 4; a++)
#pragma unroll
        for (int c = 0; c < 4; c++) acc[a][c] = 0.f;
    int t = threadIdx.x, tx = t & 15, ty = t >> 4;
    for (int k0 = 0; k0 < MM; k0 += 16) {
#pragma unroll
        for (int r = 0; r < 4; r++) {
            int idx = t + 256 * r, kk = idx >> 6, ii = idx & 63;
            As[kk][ii] = A[(k0 + kk) * NN + i0 + ii];
            Bs[kk][ii] = A[(k0 + kk) * NN + j0 + ii];
        }
        __syncthreads();
#pragma unroll
        for (int kk = 0; kk < 16; kk++) {
            float a[4], c[4];
#pragma unroll
            for (int x = 0; x < 4; x++) { a[x] = As[kk][ty + 16 * x]; c[x] = Bs[kk][tx + 16 * x]; }
#pragma unroll
            for (int ii = 0; ii < 4; ii++)
#pragma unroll
                for (int jj = 0; jj < 4; jj++) acc[ii][jj] = fmaf(a[ii], c[jj], acc[ii][jj]);
        }
        __syncthreads();
    }
    float* Mb = g_M + (size_t)b * TRI;
#pragma unroll
    for (int ii = 0; ii < 4; ii++) {
        int i = i0 + ty + 16 * ii;
#pragma unroll
        for (int jj = 0; jj < 4; jj++) {
            int j = j0 + tx + 16 * jj;
            if (j <= i) {
                float vv = RHO * acc[ii][jj];
                if (i == j) vv += Pv[b * NN + i] + SIGMA;
                Mb[offr(i) + j] = vv;
            }
        }
    }
}

// K2: per-batch Cholesky in SMEM (packed, rank-1 updates)
__global__ __launch_bounds__(1024) void k2_chol()
{
    int b = blockIdx.x, tid = threadIdx.x;
    extern __shared__ float sm2[];
    float* Ls = sm2;          // TRI
    float* col = sm2 + TRI;   // 256
    float* Mb = g_M + (size_t)b * TRI;
    for (int i = tid; i < TRI; i += 1024) Ls[i] = Mb[i];
    __syncthreads();
    int lane = tid & 31, w = tid >> 5;
    for (int k = 0; k < 256; k++) {
        float dkk = Ls[offr(k) + k];
        float s = sqrtf(dkk), rinv = 1.0f / s;
        __syncthreads();
        for (int i = k + tid; i < 256; i += 1024) {
            if (i == k) { Ls[offr(k) + k] = s; col[k] = s; }
            else { float vv = Ls[offr(i) + k] * rinv; Ls[offr(i) + k] = vv; col[i] = vv; }
        }
        __syncthreads();
        for (int i = k + 1 + w; i < 256; i += 32) {
            float ci = col[i];
            float* row = Ls + offr(i);
            for (int j = k + 1 + lane; j <= i; j += 32) row[j] = fmaf(-ci, col[j], row[j]);
        }
        __syncthreads();
    }
    for (int i = tid; i < TRI; i += 1024) Mb[i] = Ls[i];
}

// K3: Linv = L^{-1}, warp per column
__global__ __launch_bounds__(1024) void k3_trinv()
{
    int b = blockIdx.x, tid = threadIdx.x;
    extern __shared__ float sm3[];
    float* Ls = sm3;
    float* cb0 = sm3 + TRI;   // 32*256
    const float* Mb = g_M + (size_t)b * TRI;
    float* Lb = g_Linv + (size_t)b * TRI;
    for (int i = tid; i < TRI; i += 1024) Ls[i] = Mb[i];
    __syncthreads();
    int lane = tid & 31, w = tid >> 5;
    float* cb = cb0 + w * 256;
    for (int kc = w; kc < 256; kc += 32) {
        if (lane == 0) cb[kc] = 1.0f / Ls[offr(kc) + kc];
        __syncwarp();
        for (int i = kc + 1; i < 256; i++) {
            const float* row = Ls + offr(i);
            float s = 0.f;
            for (int j = kc + lane; j < i; j += 32) s = fmaf(row[j], cb[j], s);
#pragma unroll
            for (int o = 16; o; o >>= 1) s += __shfl_xor_sync(0xFFFFFFFFu, s, o);
            if (lane == 0) cb[i] = -s / row[i];
            __syncwarp();
        }
        for (int i = kc + lane; i < 256; i += 32) Lb[offr(i) + kc] = cb[i];
    }
}

// K4: Y[n][m] = sum_{j<=n} Linv[n][j]*A[m][j]
__global__ __launch_bounds__(256) void k4_Y(const float* __restrict__ Av)
{
    int b = blockIdx.z;
    int m0 = blockIdx.x * 64, n0 = blockIdx.y * 64;
    __shared__ float As[16][65], Bs[16][65];
    const float* Lb = g_Linv + (size_t)b * TRI;
    const float* A = Av + (size_t)b * (MM * NN);
    float acc[4][4];
#pragma unroll
    for (int a = 0; a < 4; a++)
#pragma unroll
        for (int c = 0; c < 4; c++) acc[a][c] = 0.f;
    int t = threadIdx.x, tx = t & 15, ty = t >> 4;
    int kmax = n0 + 64;
    for (int k0 = 0; k0 < kmax; k0 += 16) {
#pragma unroll
        for (int r = 0; r < 4; r++) {
            int idx = t + 256 * r, jj = idx & 15, nn = idx >> 4;
            int n = n0 + nn, j = k0 + jj;
            As[jj][nn] = (j <= n) ? Lb[offr(n) + j] : 0.f;
            Bs[jj][nn] = A[(m0 + nn) * NN + j];
        }
        __syncthreads();
#pragma unroll
        for (int jj = 0; jj < 16; jj++) {
            float a[4], c[4];
#pragma unroll
            for (int x = 0; x < 4; x++) { a[x] = As[jj][ty + 16 * x]; c[x] = Bs[jj][tx + 16 * x]; }
#pragma unroll
            for (int ii = 0; ii < 4; ii++)
#pragma unroll
                for (int cc = 0; cc < 4; cc++) acc[ii][cc] = fmaf(a[ii], c[cc], acc[ii][cc]);
        }
        __syncthreads();
    }
#pragma unroll
    for (int ii = 0; ii < 4; ii++) {
        int n = n0 + ty + 16 * ii;
#pragma unroll
        for (int cc = 0; cc < 4; cc++) {
            int m = m0 + tx + 16 * cc;
            g_Y[((size_t)b * NN + n) * MM + m] = acc[ii][cc];
        }
    }
}

// K4b: g = Linv * q
__global__ __launch_bounds__(256) void k4b_g(const float* __restrict__ qv)
{
    int b = blockIdx.x, tid = threadIdx.x;
    __shared__ float sq[NN];
    sq[tid] = qv[b * NN + tid];
    __syncthreads();
    int lane = tid & 31, w = tid >> 5;
    const float* Lb = g_Linv + (size_t)b * TRI;
    for (int i = w; i < NN; i += 8) {
        const float* row = Lb + offr(i);
        float s = 0.f;
        for (int j = lane; j <= i; j += 32) s = fmaf(row[j], sq[j], s);
#pragma unroll
        for (int o = 16; o; o >>= 1) s += __shfl_xor_sync(0xFFFFFFFFu, s, o);
        if (lane == 0) g_g[b * NN + i] = s;
    }
}

// K5: 200 ADMM iterations in z-space, fused single pass over Y per iteration.
// 512 threads = 16 warps; warp w handles rows n = w+16r; lane owns m in [lane*16,lane*16+16)
__global__ __launch_bounds__(512) void k5_iter(const float* __restrict__ lv,
                                               const float* __restrict__ uv)
{
    int b = blockIdx.x, tid = threadIdx.x;
    int lane = tid & 31, w = tid >> 5;
    __shared__ float su[MM], sz[MM], sy[MM], sl[MM], sub[MM];
    __shared__ float sg[NN], sS[NN];
    __shared__ float red[16 * MM];   // 32KB
    if (tid < NN) { sS[tid] = 0.f; sg[tid] = g_g[b * NN + tid]; }
    sz[tid] = 0.f; sy[tid] = 0.f;
    sl[tid] = lv[b * MM + tid]; sub[tid] = uv[b * MM + tid];
    __syncthreads();

    const float4* Yb4 = (const float4*)(g_Y + (size_t)b * NN * MM);
    float4* red4w = (float4*)(red + w * MM);

    for (int it = 0; it < ITERS; it++) {
        su[tid] = RHO * sz[tid] - sy[tid];
        __syncthreads();
        float4 ul[4], acc[4];
#pragma unroll
        for (int c = 0; c < 4; c++) {
            ul[c] = ((const float4*)su)[lane * 4 + c];
            acc[c] = make_float4(0.f, 0.f, 0.f, 0.f);
        }
#pragma unroll 1
        for (int r = 0; r < 16; r++) {
            int n = w + (r << 4);
            const float4* yr = Yb4 + (size_t)n * (MM / 4);
            float4 yv[4];
            float s = 0.f;
#pragma unroll
            for (int c = 0; c < 4; c++) {
                yv[c] = yr[lane * 4 + c];
                s += yv[c].x * ul[c].x + yv[c].y * ul[c].y + yv[c].z * ul[c].z + yv[c].w * ul[c].w;
            }
#pragma unroll
            for (int o = 16; o; o >>= 1) s += __shfl_xor_sync(0xFFFFFFFFu, s, o);
            s -= sg[n];                                  // v'_n
            if (lane == 0) sS[n] = (1.0f - ALPHA) * sS[n] + ALPHA * s;
#pragma unroll
            for (int c = 0; c < 4; c++) {
                acc[c].x = fmaf(s, yv[c].x, acc[c].x);
                acc[c].y = fmaf(s, yv[c].y, acc[c].y);
                acc[c].z = fmaf(s, yv[c].z, acc[c].z);
                acc[c].w = fmaf(s, yv[c].w, acc[c].w);
            }
        }
#pragma unroll
        for (int c = 0; c < 4; c++) red4w[lane * 4 + c] = acc[c];
        __syncthreads();
        {
            float zt = 0.f;
#pragma unroll
            for (int w2 = 0; w2 < 16; w2++) zt += red[w2 * MM + tid];
            float zr = ALPHA * zt + (1.0f - ALPHA) * sz[tid];
            float zc = zr + sy[tid] * (1.0f / RHO);
            float zn = fminf(fmaxf(zc, sl[tid]), sub[tid]);
            sy[tid] = sy[tid] + RHO * (zr - zn);
            sz[tid] = zn;
        }
        __syncthreads();
    }
    if (tid < NN) g_S[b * NN + tid] = sS[tid];
}

// K6: x = Linv^T * S  -> d_out
__global__ __launch_bounds__(256) void k6_final(float* __restrict__ out)
{
    int b = blockIdx.x, tid = threadIdx.x;
    int lane = tid & 31, w = tid >> 5;
    __shared__ float sS[NN];
    __shared__ float red6[8][NN];
    sS[tid] = g_S[b * NN + tid];
    __syncthreads();
    const float* Lb = g_Linv + (size_t)b * TRI;
    float acc[8];
#pragma unroll
    for (int c = 0; c < 8; c++) acc[c] = 0.f;
    for (int n = w; n < NN; n += 8) {
        const float* row = Lb + offr(n);
        float sv = sS[n];
#pragma unroll
        for (int c = 0; c < 8; c++) {
            int i = lane + 32 * c;
            if (i <= n) acc[c] = fmaf(sv, row[i], acc[c]);
        }
    }
#pragma unroll
    for (int c = 0; c < 8; c++) red6[w][lane + 32 * c] = acc[c];
    __syncthreads();
    float x = 0.f;
#pragma unroll
    for (int w2 = 0; w2 < 8; w2++) x += red6[w2][tid];
    out[b * NN + tid] = x;
}

extern "C" void kernel_launch(void* const* d_in, const int* in_sizes, int n_in,
                              void* d_out, int out_size)
{
    const float* P = (const float*)d_in[0];
    const float* q = (const float*)d_in[1];
    const float* A = (const float*)d_in[2];
    const float* l = (const float*)d_in[3];
    const float* u = (const float*)d_in[4];
    float* out = (float*)d_out;

    int smem_k2 = (TRI + 256) * 4;
    int smem_k3 = (TRI + 32 * 256) * 4;
    cudaFuncSetAttribute(k2_chol, cudaFuncAttributeMaxDynamicSharedMemorySize, smem_k2);
    cudaFuncSetAttribute(k3_trinv, cudaFuncAttributeMaxDynamicSharedMemorySize, smem_k3);

    k1_buildM<<<dim3(10, BATCH), 256>>>(P, A);
    k2_chol<<<BATCH, 1024, smem_k2>>>();
    k3_trinv<<<BATCH, 1024, smem_k3>>>();
    k4_Y<<<dim3(8, 4, BATCH), 256>>>(A);
    k4b_g<<<BATCH, 256>>>(q);
    k5_iter<<<BATCH, 512>>>(l, u);
    k6_final<<<BATCH, 256>>>(out);
}

// round 4
// speedup vs baseline: 1.2883x; 1.2883x over previous
#include <cuda_runtime.h>
#include <cooperative_groups.h>
#include <math.h>

namespace cg = cooperative_groups;

#define BATCH 64
#define NN    256
#define MM    512
#define SIGMA 1e-6f
#define RHO   0.1f
#define ALPHA 1.6f
#define ITERS 200
#define TRI   32896   // 256*257/2
#define RR    80      // Y rows resident in SMEM per half-CTA (of 128)

__device__ float g_M[BATCH * TRI];
__device__ float g_Linv[BATCH * TRI];
__device__ float g_Y[BATCH * NN * MM];
__device__ float g_g[BATCH * NN];
__device__ float g_S[BATCH * NN];

__device__ __forceinline__ int offr(int i) { return (i * (i + 1)) >> 1; }
__constant__ int c_ti[10] = {0,1,1,2,2,2,3,3,3,3};
__constant__ int c_tj[10] = {0,0,1,0,1,2,0,1,2,3};

// K1: M = diag(P)+sigma*I+rho*A^T A (packed lower). 64x64 tiles, 4x4 regs.
__global__ __launch_bounds__(256) void k1_buildM(const float* __restrict__ Pv,
                                                 const float* __restrict__ Av)
{
    int p = blockIdx.x, b = blockIdx.y;
    int i0 = c_ti[p] * 64, j0 = c_tj[p] * 64;
    __shared__ float As[16][64], Bs[16][64];
    const float* A = Av + (size_t)b * (MM * NN);
    float acc[4][4];
#pragma unroll
    for (int a = 0; a < 4; a++)
#pragma unroll
        for (int c = 0; c < 4; c++) acc[a][c] = 0.f;
    int t = threadIdx.x, tx = t & 15, ty = t >> 4;
    for (int k0 = 0; k0 < MM; k0 += 16) {
#pragma unroll
        for (int r = 0; r < 4; r++) {
            int idx = t + 256 * r, kk = idx >> 6, ii = idx & 63;
            As[kk][ii] = A[(k0 + kk) * NN + i0 + ii];
            Bs[kk][ii] = A[(k0 + kk) * NN + j0 + ii];
        }
        __syncthreads();
#pragma unroll
        for (int kk = 0; kk < 16; kk++) {
            float a[4], c[4];
#pragma unroll
            for (int x = 0; x < 4; x++) { a[x] = As[kk][ty + 16 * x]; c[x] = Bs[kk][tx + 16 * x]; }
#pragma unroll
            for (int ii = 0; ii < 4; ii++)
#pragma unroll
                for (int jj = 0; jj < 4; jj++) acc[ii][jj] = fmaf(a[ii], c[jj], acc[ii][jj]);
        }
        __syncthreads();
    }
    float* Mb = g_M + (size_t)b * TRI;
#pragma unroll
    for (int ii = 0; ii < 4; ii++) {
        int i = i0 + ty + 16 * ii;
#pragma unroll
        for (int jj = 0; jj < 4; jj++) {
            int j = j0 + tx + 16 * jj;
            if (j <= i) {
                float vv = RHO * acc[ii][jj];
                if (i == j) vv += Pv[b * NN + i] + SIGMA;
                Mb[offr(i) + j] = vv;
            }
        }
    }
}

// K2: per-batch Cholesky in SMEM (packed, rank-1 updates)
__global__ __launch_bounds__(1024) void k2_chol()
{
    int b = blockIdx.x, tid = threadIdx.x;
    extern __shared__ float sm2[];
    float* Ls = sm2;
    float* col = sm2 + TRI;
    float* Mb = g_M + (size_t)b * TRI;
    for (int i = tid; i < TRI; i += 1024) Ls[i] = Mb[i];
    __syncthreads();
    int lane = tid & 31, w = tid >> 5;
    for (int k = 0; k < 256; k++) {
        float dkk = Ls[offr(k) + k];
        float s = sqrtf(dkk), rinv = 1.0f / s;
        __syncthreads();
        for (int i = k + tid; i < 256; i += 1024) {
            if (i == k) { Ls[offr(k) + k] = s; col[k] = s; }
            else { float vv = Ls[offr(i) + k] * rinv; Ls[offr(i) + k] = vv; col[i] = vv; }
        }
        __syncthreads();
        for (int i = k + 1 + w; i < 256; i += 32) {
            float ci = col[i];
            float* row = Ls + offr(i);
            for (int j = k + 1 + lane; j <= i; j += 32) row[j] = fmaf(-ci, col[j], row[j]);
        }
        __syncthreads();
    }
    for (int i = tid; i < TRI; i += 1024) Mb[i] = Ls[i];
}

// K3: Linv = L^{-1}, warp per column
__global__ __launch_bounds__(1024) void k3_trinv()
{
    int b = blockIdx.x, tid = threadIdx.x;
    extern __shared__ float sm3[];
    float* Ls = sm3;
    float* cb0 = sm3 + TRI;
    const float* Mb = g_M + (size_t)b * TRI;
    float* Lb = g_Linv + (size_t)b * TRI;
    for (int i = tid; i < TRI; i += 1024) Ls[i] = Mb[i];
    __syncthreads();
    int lane = tid & 31, w = tid >> 5;
    float* cb = cb0 + w * 256;
    for (int kc = w; kc < 256; kc += 32) {
        if (lane == 0) cb[kc] = 1.0f / Ls[offr(kc) + kc];
        __syncwarp();
        for (int i = kc + 1; i < 256; i++) {
            const float* row = Ls + offr(i);
            float s = 0.f;
            for (int j = kc + lane; j < i; j += 32) s = fmaf(row[j], cb[j], s);
#pragma unroll
            for (int o = 16; o; o >>= 1) s += __shfl_xor_sync(0xFFFFFFFFu, s, o);
            if (lane == 0) cb[i] = -s / row[i];
            __syncwarp();
        }
        for (int i = kc + lane; i < 256; i += 32) Lb[offr(i) + kc] = cb[i];
    }
}

// K4: Y[n][m] = sum_{j<=n} Linv[n][j]*A[m][j]
__global__ __launch_bounds__(256) void k4_Y(const float* __restrict__ Av)
{
    int b = blockIdx.z;
    int m0 = blockIdx.x * 64, n0 = blockIdx.y * 64;
    __shared__ float As[16][65], Bs[16][65];
    const float* Lb = g_Linv + (size_t)b * TRI;
    const float* A = Av + (size_t)b * (MM * NN);
    float acc[4][4];
#pragma unroll
    for (int a = 0; a < 4; a++)
#pragma unroll
        for (int c = 0; c < 4; c++) acc[a][c] = 0.f;
    int t = threadIdx.x, tx = t & 15, ty = t >> 4;
    int kmax = n0 + 64;
    for (int k0 = 0; k0 < kmax; k0 += 16) {
#pragma unroll
        for (int r = 0; r < 4; r++) {
            int idx = t + 256 * r, jj = idx & 15, nn = idx >> 4;
            int n = n0 + nn, j = k0 + jj;
            As[jj][nn] = (j <= n) ? Lb[offr(n) + j] : 0.f;
            Bs[jj][nn] = A[(m0 + nn) * NN + j];
        }
        __syncthreads();
#pragma unroll
        for (int jj = 0; jj < 16; jj++) {
            float a[4], c[4];
#pragma unroll
            for (int x = 0; x < 4; x++) { a[x] = As[jj][ty + 16 * x]; c[x] = Bs[jj][tx + 16 * x]; }
#pragma unroll
            for (int ii = 0; ii < 4; ii++)
#pragma unroll
                for (int cc = 0; cc < 4; cc++) acc[ii][cc] = fmaf(a[ii], c[cc], acc[ii][cc]);
        }
        __syncthreads();
    }
#pragma unroll
    for (int ii = 0; ii < 4; ii++) {
        int n = n0 + ty + 16 * ii;
#pragma unroll
        for (int cc = 0; cc < 4; cc++) {
            int m = m0 + tx + 16 * cc;
            g_Y[((size_t)b * NN + n) * MM + m] = acc[ii][cc];
        }
    }
}

// K4b: g = Linv * q
__global__ __launch_bounds__(256) void k4b_g(const float* __restrict__ qv)
{
    int b = blockIdx.x, tid = threadIdx.x;
    __shared__ float sq[NN];
    sq[tid] = qv[b * NN + tid];
    __syncthreads();
    int lane = tid & 31, w = tid >> 5;
    const float* Lb = g_Linv + (size_t)b * TRI;
    for (int i = w; i < NN; i += 8) {
        const float* row = Lb + offr(i);
        float s = 0.f;
        for (int j = lane; j <= i; j += 32) s = fmaf(row[j], sq[j], s);
#pragma unroll
        for (int o = 16; o; o >>= 1) s += __shfl_xor_sync(0xFFFFFFFFu, s, o);
        if (lane == 0) g_g[b * NN + i] = s;
    }
}

// ---- K5: one iteration pair-step, residency resolved at compile time ----
template<bool R0, bool R1>
__device__ __forceinline__ void pair_step(int n0, int n1, int lane,
    const float4* __restrict__ sY4, const float4* __restrict__ Yg4,
    const float4 ul[4], float4 acc[4], const float* __restrict__ sg,
    float* __restrict__ sS)
{
    float4 y0[4], y1[4];
#pragma unroll
    for (int c = 0; c < 4; c++) {
        if (R0) y0[c] = sY4[n0 * 128 + lane * 4 + c];
        else    y0[c] = Yg4[n0 * 128 + lane * 4 + c];
        if (R1) y1[c] = sY4[n1 * 128 + lane * 4 + c];
        else    y1[c] = Yg4[n1 * 128 + lane * 4 + c];
    }
    float s0 = 0.f, s1 = 0.f;
#pragma unroll
    for (int c = 0; c < 4; c++) {
        s0 += y0[c].x * ul[c].x + y0[c].y * ul[c].y + y0[c].z * ul[c].z + y0[c].w * ul[c].w;
        s1 += y1[c].x * ul[c].x + y1[c].y * ul[c].y + y1[c].z * ul[c].z + y1[c].w * ul[c].w;
    }
#pragma unroll
    for (int o = 16; o; o >>= 1) {
        s0 += __shfl_xor_sync(0xFFFFFFFFu, s0, o);
        s1 += __shfl_xor_sync(0xFFFFFFFFu, s1, o);
    }
    s0 -= sg[n0]; s1 -= sg[n1];
    if (lane == 0) {
        sS[n0] = (1.0f - ALPHA) * sS[n0] + ALPHA * s0;
        sS[n1] = (1.0f - ALPHA) * sS[n1] + ALPHA * s1;
    }
#pragma unroll
    for (int c = 0; c < 4; c++) {
        acc[c].x = fmaf(s0, y0[c].x, fmaf(s1, y1[c].x, acc[c].x));
        acc[c].y = fmaf(s0, y0[c].y, fmaf(s1, y1[c].y, acc[c].y));
        acc[c].z = fmaf(s0, y0[c].z, fmaf(s1, y1[c].z, acc[c].z));
        acc[c].w = fmaf(s0, y0[c].w, fmaf(s1, y1[c].w, acc[c].w));
    }
}

// K5: 200 ADMM iterations. 2 CTAs (cluster) per batch item; each owns 128 Y rows,
// 80 of them SMEM-resident. Per-iter DSMEM exchange of partial z~.
#define SM5_FLOATS (RR * 512 + 16 * 512 + 5 * 512 + 2 * 512 + 256)
__global__ __cluster_dims__(2, 1, 1) __launch_bounds__(512)
void k5_iter(const float* __restrict__ lv, const float* __restrict__ uv)
{
    cg::cluster_group cluster = cg::this_cluster();
    int b = blockIdx.x >> 1, half = blockIdx.x & 1;
    int tid = threadIdx.x, lane = tid & 31;
    int w = (threadIdx.x >> 5) & 15;
    extern __shared__ float sm5[];
    float* sY   = sm5;                   // RR*512
    float* red  = sY + RR * 512;         // 16*512
    float* su   = red + 16 * 512;        // 512
    float* sz   = su + 512;              // 512
    float* sy   = sz + 512;              // 512
    float* sl   = sy + 512;              // 512
    float* sub  = sl + 512;              // 512
    float* sbuf = sub + 512;             // 2*512 (peer writes here)
    float* sg   = sbuf + 1024;           // 128
    float* sS   = sg + 128;              // 128

    const float* Yg = g_Y + ((size_t)b * NN + half * 128) * MM;
    const float4* Yg4 = (const float4*)Yg;
    // stage resident rows [0, RR)
    for (int i = tid; i < RR * 128; i += 512)
        ((float4*)sY)[i] = Yg4[i];
    if (tid < 128) {
        sg[tid] = g_g[b * NN + half * 128 + tid];
        sS[tid] = 0.f;
    }
    sz[tid] = 0.f; sy[tid] = 0.f;
    sl[tid] = lv[b * MM + tid]; sub[tid] = uv[b * MM + tid];
    __syncthreads();

    float* peerbuf = cluster.map_shared_rank(sbuf, half ^ 1);
    const float4* sY4 = (const float4*)sY;
    const float4* su4 = (const float4*)su;
    float4* redw = (float4*)(red + w * 512);

    for (int it = 0; it < ITERS; it++) {
        su[tid] = RHO * sz[tid] - sy[tid];
        __syncthreads();
        float4 ul[4];
#pragma unroll
        for (int c = 0; c < 4; c++) ul[c] = su4[lane * 4 + c];
        float4 acc[4];
#pragma unroll
        for (int c = 0; c < 4; c++) acc[c] = make_float4(0.f, 0.f, 0.f, 0.f);

        pair_step<true,  true >(w,      w + 16,  lane, sY4, Yg4, ul, acc, sg, sS);
        pair_step<true,  true >(w + 32, w + 48,  lane, sY4, Yg4, ul, acc, sg, sS);
        pair_step<true,  false>(w + 64, w + 80,  lane, sY4, Yg4, ul, acc, sg, sS);
        pair_step<false, false>(w + 96, w + 112, lane, sY4, Yg4, ul, acc, sg, sS);

#pragma unroll
        for (int c = 0; c < 4; c++) redw[lane * 4 + c] = acc[c];
        __syncthreads();
        float mypart = 0.f;
#pragma unroll
        for (int w2 = 0; w2 < 16; w2++) mypart += red[w2 * 512 + tid];
        peerbuf[(it & 1) * 512 + tid] = mypart;
        cluster.sync();
        float zt = mypart + sbuf[(it & 1) * 512 + tid];
        float zr = ALPHA * zt + (1.0f - ALPHA) * sz[tid];
        float zc = zr + sy[tid] * (1.0f / RHO);
        float zn = fminf(fmaxf(zc, sl[tid]), sub[tid]);
        sy[tid] = sy[tid] + RHO * (zr - zn);
        sz[tid] = zn;
        // sz/sy updates are tid-local; next iteration's __syncthreads orders su.
    }
    if (tid < 128) g_S[b * NN + half * 128 + tid] = sS[tid];
}

// K6: x = Linv^T * S  -> d_out
__global__ __launch_bounds__(256) void k6_final(float* __restrict__ out)
{
    int b = blockIdx.x, tid = threadIdx.x;
    int lane = tid & 31, w = tid >> 5;
    __shared__ float sS[NN];
    __shared__ float red6[8][NN];
    sS[tid] = g_S[b * NN + tid];
    __syncthreads();
    const float* Lb = g_Linv + (size_t)b * TRI;
    float acc[8];
#pragma unroll
    for (int c = 0; c < 8; c++) acc[c] = 0.f;
    for (int n = w; n < NN; n += 8) {
        const float* row = Lb + offr(n);
        float sv = sS[n];
#pragma unroll
        for (int c = 0; c < 8; c++) {
            int i = lane + 32 * c;
            if (i <= n) acc[c] = fmaf(sv, row[i], acc[c]);
        }
    }
#pragma unroll
    for (int c = 0; c < 8; c++) red6[w][lane + 32 * c] = acc[c];
    __syncthreads();
    float x = 0.f;
#pragma unroll
    for (int w2 = 0; w2 < 8; w2++) x += red6[w2][tid];
    out[b * NN + tid] = x;
}

extern "C" void kernel_launch(void* const* d_in, const int* in_sizes, int n_in,
                              void* d_out, int out_size)
{
    const float* P = (const float*)d_in[0];
    const float* q = (const float*)d_in[1];
    const float* A = (const float*)d_in[2];
    const float* l = (const float*)d_in[3];
    const float* u = (const float*)d_in[4];
    float* out = (float*)d_out;

    int smem_k2 = (TRI + 256) * 4;
    int smem_k3 = (TRI + 32 * 256) * 4;
    int smem_k5 = SM5_FLOATS * 4;   // 211,968 B
    cudaFuncSetAttribute(k2_chol, cudaFuncAttributeMaxDynamicSharedMemorySize, smem_k2);
    cudaFuncSetAttribute(k3_trinv, cudaFuncAttributeMaxDynamicSharedMemorySize, smem_k3);
    cudaFuncSetAttribute(k5_iter, cudaFuncAttributeMaxDynamicSharedMemorySize, smem_k5);

    k1_buildM<<<dim3(10, BATCH), 256>>>(P, A);
    k2_chol<<<BATCH, 1024, smem_k2>>>();
    k3_trinv<<<BATCH, 1024, smem_k3>>>();
    k4_Y<<<dim3(8, 4, BATCH), 256>>>(A);
    k4b_g<<<BATCH, 256>>>(q);
    k5_iter<<<BATCH * 2, 512, smem_k5>>>(l, u);
    k6_final<<<BATCH, 256>>>(out);
}